// round 2
// baseline (speedup 1.0000x reference)
#include <cuda_runtime.h>
#include <math.h>

#define NTOK 8192
#define DM   1024
#define HM   2048
#define NEXP 8
#define CAP  8192

// ---------------- device scratch (static globals: allocation-free) ----------
__device__ int   g_cnt[NEXP];
__device__ float g_Psum[NEXP];
__device__ int   g_tok[NEXP * CAP];
__device__ float g_wt [NEXP * CAP];
// h scratch: routed experts need up to NEXP*CAP*HM; shared expert reuses the
// front of the same buffer (strictly sequenced on the stream before routed use).
__device__ float g_h[(size_t)NEXP * CAP * HM];

// ---------------- init ------------------------------------------------------
__global__ void init_kernel() {
    int i = threadIdx.x;
    if (i < NEXP) { g_cnt[i] = 0; g_Psum[i] = 0.f; }
}

// ---------------- router ----------------------------------------------------
// One warp per token. Wr (D x E) staged in smem.
__global__ void router_kernel(const float* __restrict__ x,
                              const float* __restrict__ Wr) {
    __shared__ float sW[DM * NEXP];
    for (int i = threadIdx.x; i < DM * NEXP; i += blockDim.x) sW[i] = Wr[i];
    __syncthreads();

    int warp = threadIdx.x >> 5, lane = threadIdx.x & 31;
    int t = blockIdx.x * 8 + warp;
    if (t >= NTOK) return;

    const float* xr = x + (size_t)t * DM;
    float acc[NEXP];
#pragma unroll
    for (int e = 0; e < NEXP; e++) acc[e] = 0.f;
    for (int d = lane; d < DM; d += 32) {
        float xv = xr[d];
        const float* w = &sW[d * NEXP];
#pragma unroll
        for (int e = 0; e < NEXP; e++) acc[e] += xv * w[e];
    }
#pragma unroll
    for (int o = 16; o > 0; o >>= 1)
#pragma unroll
        for (int e = 0; e < NEXP; e++)
            acc[e] += __shfl_xor_sync(0xffffffffu, acc[e], o);
    if (lane) return;

    // top-2 (first-index wins ties, matching lax.top_k)
    int e1 = 0; float l1 = acc[0];
#pragma unroll
    for (int e = 1; e < NEXP; e++) if (acc[e] > l1) { l1 = acc[e]; e1 = e; }
    int e2 = -1; float l2 = -3.4e38f;
#pragma unroll
    for (int e = 0; e < NEXP; e++)
        if (e != e1 && acc[e] > l2) { l2 = acc[e]; e2 = e; }

    // full softmax for P (max is l1)
    float p[NEXP], s = 0.f;
#pragma unroll
    for (int e = 0; e < NEXP; e++) { p[e] = expf(acc[e] - l1); s += p[e]; }
    float inv = 1.f / s;
#pragma unroll
    for (int e = 0; e < NEXP; e++) atomicAdd(&g_Psum[e], p[e] * inv);

    // softmax over the top-2 logits
    float r  = expf(l2 - l1);
    float w1 = 1.f / (1.f + r);
    float w2 = r * w1;

    int p1 = atomicAdd(&g_cnt[e1], 1);
    g_tok[e1 * CAP + p1] = t;  g_wt[e1 * CAP + p1] = w1;
    int p2 = atomicAdd(&g_cnt[e2], 1);
    g_tok[e2 * CAP + p2] = t;  g_wt[e2 * CAP + p2] = w2;
}

// ---------------- FFN1: h = silu(X @ Wg) * (X @ Wu) -------------------------
// Tile 128x64, BK=16, 256 threads, dual-B accumulation.
template <bool ROUTED>
__global__ void ffn1_kernel(const float* __restrict__ X,
                            const float* __restrict__ Wg,
                            const float* __restrict__ Wu) {
    const int BM = 128, BN = 64, BK = 16;
    int e    = ROUTED ? blockIdx.z : 0;
    int M    = ROUTED ? g_cnt[e]   : NTOK;
    int row0 = blockIdx.y * BM;
    if (row0 >= M) return;
    int col0 = blockIdx.x * BN;

    const int*   tok = ROUTED ? (g_tok + e * CAP) : (const int*)nullptr;
    const float* Bg  = Wg + (size_t)e * DM * HM;
    const float* Bu  = Wu + (size_t)e * DM * HM;
    float* Hout = g_h + (ROUTED ? (size_t)e * CAP * HM : (size_t)0);

    __shared__ float As [BK][BM + 4];
    __shared__ float Bgs[BK][BN];
    __shared__ float Bus[BK][BN];

    int tid = threadIdx.x;
    int tx = tid & 15, ty = tid >> 4;

    int arow[2]; size_t abase[2];
#pragma unroll
    for (int r = 0; r < 2; r++) {
        int id = tid + r * 256;
        arow[r] = id >> 2;
        int m = row0 + arow[r];
        int tt = ROUTED ? ((m < M) ? tok[m] : 0) : ((m < M) ? m : 0);
        abase[r] = (size_t)tt * DM + (size_t)((id & 3) * 4);
    }
    int brow = tid >> 4, bcol = (tid & 15) * 4;

    float accg[8][4], accu[8][4];
#pragma unroll
    for (int i = 0; i < 8; i++)
#pragma unroll
        for (int j = 0; j < 4; j++) { accg[i][j] = 0.f; accu[i][j] = 0.f; }

    for (int kt = 0; kt < DM; kt += BK) {
#pragma unroll
        for (int r = 0; r < 2; r++) {
            int id = tid + r * 256;
            int kk = (id & 3) * 4;
            float4 v = *(const float4*)(X + abase[r] + kt);
            As[kk + 0][arow[r]] = v.x;  As[kk + 1][arow[r]] = v.y;
            As[kk + 2][arow[r]] = v.z;  As[kk + 3][arow[r]] = v.w;
        }
        {
            size_t off = (size_t)(kt + brow) * HM + col0 + bcol;
            *(float4*)&Bgs[brow][bcol] = *(const float4*)(Bg + off);
            *(float4*)&Bus[brow][bcol] = *(const float4*)(Bu + off);
        }
        __syncthreads();
#pragma unroll
        for (int k = 0; k < BK; k++) {
            float4 a0 = *(float4*)&As[k][ty * 8];
            float4 a1 = *(float4*)&As[k][ty * 8 + 4];
            float4 bg = *(float4*)&Bgs[k][tx * 4];
            float4 bu = *(float4*)&Bus[k][tx * 4];
            float a[8] = {a0.x, a0.y, a0.z, a0.w, a1.x, a1.y, a1.z, a1.w};
            float bgv[4] = {bg.x, bg.y, bg.z, bg.w};
            float buv[4] = {bu.x, bu.y, bu.z, bu.w};
#pragma unroll
            for (int i = 0; i < 8; i++)
#pragma unroll
                for (int j = 0; j < 4; j++) {
                    accg[i][j] += a[i] * bgv[j];
                    accu[i][j] += a[i] * buv[j];
                }
        }
        __syncthreads();
    }

#pragma unroll
    for (int i = 0; i < 8; i++) {
        int m = row0 + ty * 8 + i;
        if (m >= M) continue;
        float4 o;
        float g;
        g = accg[i][0]; o.x = (g / (1.f + expf(-g))) * accu[i][0];
        g = accg[i][1]; o.y = (g / (1.f + expf(-g))) * accu[i][1];
        g = accg[i][2]; o.z = (g / (1.f + expf(-g))) * accu[i][2];
        g = accg[i][3]; o.w = (g / (1.f + expf(-g))) * accu[i][3];
        *(float4*)(Hout + (size_t)m * HM + col0 + tx * 4) = o;
    }
}

// ---------------- FFN2: y = h @ Wd ; scatter/store --------------------------
template <bool ROUTED>
__global__ void ffn2_kernel(const float* __restrict__ Wd,
                            float* __restrict__ out) {
    const int BM = 128, BN = 64, BK = 16;
    int e    = ROUTED ? blockIdx.z : 0;
    int M    = ROUTED ? g_cnt[e]   : NTOK;
    int row0 = blockIdx.y * BM;
    if (row0 >= M) return;
    int col0 = blockIdx.x * BN;

    const float* A = g_h + (ROUTED ? (size_t)e * CAP * HM : (size_t)0);
    const float* B = Wd + (size_t)e * HM * DM;

    __shared__ float As[BK][BM + 4];
    __shared__ float Bs[BK][BN];

    int tid = threadIdx.x;
    int tx = tid & 15, ty = tid >> 4;

    int arow[2]; size_t abase[2];
#pragma unroll
    for (int r = 0; r < 2; r++) {
        int id = tid + r * 256;
        arow[r] = id >> 2;
        int m = row0 + arow[r];
        int mm = (m < M) ? m : 0;
        abase[r] = (size_t)mm * HM + (size_t)((id & 3) * 4);
    }
    int brow = tid >> 4, bcol = (tid & 15) * 4;

    float acc[8][4];
#pragma unroll
    for (int i = 0; i < 8; i++)
#pragma unroll
        for (int j = 0; j < 4; j++) acc[i][j] = 0.f;

    for (int kt = 0; kt < HM; kt += BK) {
#pragma unroll
        for (int r = 0; r < 2; r++) {
            int id = tid + r * 256;
            int kk = (id & 3) * 4;
            float4 v = *(const float4*)(A + abase[r] + kt);
            As[kk + 0][arow[r]] = v.x;  As[kk + 1][arow[r]] = v.y;
            As[kk + 2][arow[r]] = v.z;  As[kk + 3][arow[r]] = v.w;
        }
        {
            size_t off = (size_t)(kt + brow) * DM + col0 + bcol;
            *(float4*)&Bs[brow][bcol] = *(const float4*)(B + off);
        }
        __syncthreads();
#pragma unroll
        for (int k = 0; k < BK; k++) {
            float4 a0 = *(float4*)&As[k][ty * 8];
            float4 a1 = *(float4*)&As[k][ty * 8 + 4];
            float4 b  = *(float4*)&Bs[k][tx * 4];
            float a[8] = {a0.x, a0.y, a0.z, a0.w, a1.x, a1.y, a1.z, a1.w};
            float bv[4] = {b.x, b.y, b.z, b.w};
#pragma unroll
            for (int i = 0; i < 8; i++)
#pragma unroll
                for (int j = 0; j < 4; j++) acc[i][j] += a[i] * bv[j];
        }
        __syncthreads();
    }

#pragma unroll
    for (int i = 0; i < 8; i++) {
        int m = row0 + ty * 8 + i;
        if (m >= M) continue;
        if (ROUTED) {
            float w = g_wt[e * CAP + m];
            int   t = g_tok[e * CAP + m];
            float* dst = out + (size_t)t * DM + col0 + tx * 4;
            atomicAdd(dst + 0, w * acc[i][0]);
            atomicAdd(dst + 1, w * acc[i][1]);
            atomicAdd(dst + 2, w * acc[i][2]);
            atomicAdd(dst + 3, w * acc[i][3]);
        } else {
            float4 o = make_float4(acc[i][0], acc[i][1], acc[i][2], acc[i][3]);
            *(float4*)(out + (size_t)m * DM + col0 + tx * 4) = o;
        }
    }
}

// ---------------- aux loss --------------------------------------------------
__global__ void aux_kernel(float* __restrict__ out, int out_size) {
    if (out_size <= NTOK * DM) return;
    if (threadIdx.x != 0) return;
    float aux = 0.f;
    for (int e = 0; e < NEXP; e++)
        aux += ((float)g_cnt[e] / (NTOK * 2.0f)) * (g_Psum[e] / (float)NTOK);
    out[NTOK * DM] = aux * (float)NEXP;
}

// ---------------- launch ----------------------------------------------------
extern "C" void kernel_launch(void* const* d_in, const int* in_sizes, int n_in,
                              void* d_out, int out_size) {
    const float* x   = (const float*)d_in[0];
    const float* Wr  = (const float*)d_in[1];
    const float* Wg  = (const float*)d_in[2];
    const float* Wu  = (const float*)d_in[3];
    const float* Wd  = (const float*)d_in[4];
    const float* sWg = (const float*)d_in[5];
    const float* sWu = (const float*)d_in[6];
    const float* sWd = (const float*)d_in[7];
    float* out = (float*)d_out;

    init_kernel<<<1, 32>>>();
    router_kernel<<<NTOK / 8, 256>>>(x, Wr);

    // shared expert first: plain stores initialize out[0 .. N*D)
    ffn1_kernel<false><<<dim3(HM / 64, NTOK / 128), 256>>>(x, sWg, sWu);
    ffn2_kernel<false><<<dim3(DM / 64, NTOK / 128), 256>>>(sWd, out);

    // routed experts: atomic accumulate
    ffn1_kernel<true><<<dim3(HM / 64, CAP / 128, NEXP), 256>>>(x, Wg, Wu);
    ffn2_kernel<true><<<dim3(DM / 64, CAP / 128, NEXP), 256>>>(Wd, out);

    aux_kernel<<<1, 32>>>(out, out_size);
}